// round 2
// baseline (speedup 1.0000x reference)
#include <cuda_runtime.h>
#include <stdint.h>

// Problem constants
#define S_LEN   2048
#define PATCH   16
#define NWIN    2033            // S_LEN - PATCH + 1
#define ND      4
#define NCAND   (ND * NWIN)     // 8132
#define NB      32
#define NC      8
#define NROWS   (NB * NC)       // 256
#define NT      512             // threads in row kernel
#define CH      16              // chunk per thread (NT*CH = 8192 >= NCAND)
#define SXX_CONST 2728.0f       // sum_{k=0}^{31} (k-15.5)^2

// Scratch (static device globals; allocation-free)
__device__ float    g_conv[(size_t)NROWS * ND * S_LEN];   // 8 MB, L2-resident
__device__ uint32_t g_src[(size_t)NROWS * NCAND];         // 8.3 MB packed gather codes

// Shared memory layout (bytes):
//  xs   : 2048 f       [0, 8192)
//  cv   : 8192 f       [8192, 40960)
//  ws   : 64 f         [40960, 41216)
//  wb   : 4 f          [41216, 41232)
//  cm   : 8132 B       [41232, 49364)
//  fs   : 512 int      [49364, 51412)
//  cnts : 513 int      [51412, 53464)
#define SMEM_BYTES 53464

__global__ __launch_bounds__(NT) void k_row(
    const float* __restrict__ seasonal,
    const float* __restrict__ conv_w,
    const float* __restrict__ conv_b)
{
    extern __shared__ unsigned char smem_raw[];
    float*   xs   = (float*)smem_raw;
    float*   cv   = xs + S_LEN;
    float*   ws   = cv + ND * S_LEN;
    float*   wb   = ws + 64;
    uint8_t* cm   = (uint8_t*)(wb + 4);
    int*     fs   = (int*)(cm + ((NCAND + 3) & ~3));
    int*     cnts = fs + NT;

    const int row = blockIdx.x;          // 0..255 = b*8 + c
    const int b   = row >> 3;
    const int c   = row & 7;
    const int tid = threadIdx.x;

    // ---- stage weights + input row ----
    if (tid < 64) ws[tid] = conv_w[tid];
    if (tid < 4)  wb[tid] = conv_b[tid];
    for (int s = tid; s < S_LEN; s += NT)
        xs[s] = seasonal[((size_t)b * S_LEN + s) * NC + c];
    __syncthreads();

    // ---- dilated conv: o_d[t] = b_d + sum_k w_d[k] * x[t - (15-k)*d] ----
    float* grow = g_conv + (size_t)row * ND * S_LEN;
    for (int idx = tid; idx < ND * S_LEN; idx += NT) {
        int di  = idx >> 11;
        int t   = idx & (S_LEN - 1);
        int dil = 1 << di;               // dilations 1,2,4,8
        float acc = wb[di];
        #pragma unroll
        for (int k = 0; k < PATCH; k++) {
            int j = t - (15 - k) * dil;
            float xv = (j >= 0) ? xs[j] : 0.0f;
            acc = fmaf(ws[di * PATCH + k], xv, acc);
        }
        cv[idx]   = acc;
        grow[idx] = acc;
    }
    __syncthreads();

    // ---- can_merge[i]: R^2 of 32-vector [win(i), win(i+1)] vs line >= 0.5 ----
    for (int i = tid; i < NCAND - 1; i += NT) {
        int d1 = i / NWIN;
        int t1 = i - d1 * NWIN;
        int d2 = d1, t2 = t1 + 1;
        if (t2 == NWIN) { d2 = d1 + 1; t2 = 0; }
        const float* w1 = cv + d1 * S_LEN + t1;
        const float* w2 = cv + d2 * S_LEN + t2;
        float y[32];
        #pragma unroll
        for (int k = 0; k < 16; k++) { y[k] = w1[k]; y[16 + k] = w2[k]; }
        float sy = 0.f;
        #pragma unroll
        for (int k = 0; k < 32; k++) sy += y[k];
        float mean = sy * (1.0f / 32.0f);
        float syy = 0.f, sxy = 0.f;
        #pragma unroll
        for (int k = 0; k < 32; k++) {
            float v = y[k] - mean;
            syy = fmaf(v, v, syy);
            sxy = fmaf(v, (float)k - 15.5f, sxy);
        }
        float r2 = (sxy * sxy) / (SXX_CONST * syy);   // syy==0 -> NaN -> false
        cm[i] = (r2 >= 0.5f) ? 1 : 0;
    }
    if (tid == 0) cm[NCAND - 1] = 0;     // padded False
    __syncthreads();

    // ---- merge scan: consumed_i = cm_i & ~consumed_{i-1}.
    // Each element is s -> (s&a)^b with (a,b) = (cm,cm); compose per chunk. ----
    const int base = tid * CH;
    int a = 1, bf = 0;                   // identity
    #pragma unroll
    for (int q = 0; q < CH; q++) {
        int i  = base + q;
        int ci = (i < NCAND) ? cm[i] : 0;
        bf = (bf & ci) ^ ci;             // b' = (b & a2) ^ b2, a2=b2=ci
        a &= ci;
    }
    fs[tid] = a | (bf << 1);
    __syncthreads();
    if (tid == 0) {                      // exclusive scan of function composition
        int s = 0;
        for (int t = 0; t < NT; t++) {
            int f = fs[t];
            fs[t] = s;
            s = (s & (f & 1)) ^ ((f >> 1) & 1);
        }
    }
    __syncthreads();

    int s = fs[tid];                     // incoming consumed state
    uint32_t mbits = 0, vbits = 0;
    int cnt = 0;
    #pragma unroll
    for (int q = 0; q < CH; q++) {
        int i = base + q;
        if (i >= NCAND) break;
        int v  = s ^ 1;                  // valid = !consumed
        int mg = v & cm[i];              // merge
        mbits |= (uint32_t)mg << q;
        vbits |= (uint32_t)v  << q;
        cnt += v;
        s = mg;
    }
    cnts[tid] = cnt;
    __syncthreads();
    if (tid == 0) {                      // exclusive scan of valid counts
        int acc = 0;
        for (int t = 0; t < NT; t++) { int x = cnts[t]; cnts[t] = acc; acc += x; }
        cnts[NT] = acc;
    }
    __syncthreads();

    // ---- compaction: packed gather codes (t:12 | d:2 | merged:1) ----
    int pos = cnts[tid];
    uint32_t* srow = g_src + (size_t)row * NCAND;
    for (int q = 0; q < CH; q++) {
        int i = base + q;
        if (i >= NCAND) break;
        if ((vbits >> q) & 1) {
            int d1 = i / NWIN;
            int t1 = i - d1 * NWIN;
            uint32_t code = (uint32_t)t1 | ((uint32_t)d1 << 12)
                          | (((mbits >> q) & 1u) << 14);
            srow[pos++] = code;
        }
    }
    int V = cnts[NT];
    for (int j = V + tid; j < NCAND; j += NT) srow[j] = 0xFFFFFFFFu;
}

// ---- output gather + transpose: out[b, n, k, c], c fastest.
// One thread per (b, n, k): gathers 8 channels, stores 32B (two float4). ----
__global__ __launch_bounds__(256) void k_out(float* __restrict__ out)
{
    int b  = blockIdx.y;
    int id = blockIdx.x * 256 + threadIdx.x;
    int k  = id & 15;
    int n  = id >> 4;
    if (n >= NCAND) return;

    float buf[8];
    #pragma unroll
    for (int c = 0; c < 8; c++) {
        int row = b * 8 + c;
        uint32_t code = g_src[(size_t)row * NCAND + n];
        float v = 0.0f;
        if (code != 0xFFFFFFFFu) {
            int t1 = code & 0xFFF;
            int d1 = (code >> 12) & 3;
            const float* cr = g_conv + (size_t)row * ND * S_LEN;
            v = cr[d1 * S_LEN + t1 + k];
            if (code & (1u << 14)) {                 // merged with next candidate
                int t2 = t1 + 1, d2 = d1;
                if (t2 == NWIN) { t2 = 0; d2 = d1 + 1; }
                v = 0.5f * (v + cr[d2 * S_LEN + t2 + k]);
            }
        }
        buf[c] = v;
    }
    size_t obase = ((size_t)((b * NCAND + n) * PATCH + k)) * 8;
    float4* o = (float4*)(out + obase);
    o[0] = make_float4(buf[0], buf[1], buf[2], buf[3]);
    o[1] = make_float4(buf[4], buf[5], buf[6], buf[7]);
}

extern "C" void kernel_launch(void* const* d_in, const int* in_sizes, int n_in,
                              void* d_out, int out_size)
{
    const float* seasonal = (const float*)d_in[0];
    const float* cw       = (const float*)d_in[1];
    const float* cb       = (const float*)d_in[2];
    float* out = (float*)d_out;

    cudaFuncSetAttribute(k_row, cudaFuncAttributeMaxDynamicSharedMemorySize,
                         SMEM_BYTES);
    k_row<<<NROWS, NT, SMEM_BYTES>>>(seasonal, cw, cb);

    dim3 g((NCAND * PATCH + 255) / 256, NB);
    k_out<<<g, 256>>>(out);
}

// round 4
// speedup vs baseline: 1.0506x; 1.0506x over previous
#include <cuda_runtime.h>
#include <stdint.h>

// Problem constants
#define S_LEN   2048
#define PATCH   16
#define NWIN    2033            // S_LEN - PATCH + 1
#define ND      4
#define NCAND   (ND * NWIN)     // 8132
#define NB      32
#define NC      8
#define NROWS   (NB * NC)       // 256
#define NT      512             // threads in row kernel
#define NWARP   (NT / 32)       // 16
#define CH      16              // chunk per thread (NT*CH = 8192 >= NCAND)
#define SXX_CONST 2728.0f       // sum_{k=0}^{31} (k-15.5)^2

// Scratch (static device globals; allocation-free)
__device__ float    g_conv[(size_t)NROWS * ND * S_LEN];   // 8 MB, L2-resident
__device__ uint32_t g_src[(size_t)NROWS * NCAND];         // 8.3 MB packed gather codes

// Shared layout for k_row (bytes):
//  xs   : 2048 f   cv : 8192 f   ws : 64 f   wb : 4 f
//  cm   : 8132 B (pad 8136)   warpf : 16 int   warpc : 17 int
#define SMEM_BYTES (8192 + 32768 + 256 + 16 + 8136 + 64 + 68 + 64)

// affine bit-function f(s) = (s & a) ^ b, packed as a | (b<<1).
// fcomb(first, second) = second ∘ first (apply first, then second).
__device__ __forceinline__ int fcomb(int f1, int f2) {
    int a1 = f1 & 1, b1 = (f1 >> 1) & 1;
    int a2 = f2 & 1, b2 = (f2 >> 1) & 1;
    return (a1 & a2) | ((((b1 & a2) ^ b2)) << 1);
}

__global__ __launch_bounds__(NT) void k_row(
    const float* __restrict__ seasonal,
    const float* __restrict__ conv_w,
    const float* __restrict__ conv_b)
{
    extern __shared__ unsigned char smem_raw[];
    float*   xs    = (float*)smem_raw;
    float*   cv    = xs + S_LEN;
    float*   ws    = cv + ND * S_LEN;
    float*   wb    = ws + 64;
    uint8_t* cm    = (uint8_t*)(wb + 4);
    int*     warpf = (int*)(cm + 8136);
    int*     warpc = warpf + NWARP;     // [NWARP+1]: +1 holds total

    const int row  = blockIdx.x;         // 0..255 = b*8 + c
    const int b    = row >> 3;
    const int c    = row & 7;
    const int tid  = threadIdx.x;
    const int lane = tid & 31;
    const int wid  = tid >> 5;

    // ---- stage weights + input row ----
    if (tid < 64) ws[tid] = conv_w[tid];
    if (tid < 4)  wb[tid] = conv_b[tid];
    for (int s = tid; s < S_LEN; s += NT)
        xs[s] = seasonal[((size_t)b * S_LEN + s) * NC + c];
    __syncthreads();

    // ---- dilated conv: o_d[t] = b_d + sum_k w_d[k] * x[t - (15-k)*d] ----
    float* grow = g_conv + (size_t)row * ND * S_LEN;
    for (int idx = tid; idx < ND * S_LEN; idx += NT) {
        int di  = idx >> 11;
        int t   = idx & (S_LEN - 1);
        int dil = 1 << di;
        float acc = wb[di];
        #pragma unroll
        for (int k = 0; k < PATCH; k++) {
            int j = t - (15 - k) * dil;
            float xv = (j >= 0) ? xs[j] : 0.0f;
            acc = fmaf(ws[di * PATCH + k], xv, acc);
        }
        cv[idx]   = acc;
        grow[idx] = acc;
    }
    __syncthreads();

    // ---- can_merge[i]: R^2 of [win(i), win(i+1)] vs line >= 0.5 ----
    for (int i = tid; i < NCAND - 1; i += NT) {
        int d1 = i / NWIN;
        int t1 = i - d1 * NWIN;
        int d2 = d1, t2 = t1 + 1;
        if (t2 == NWIN) { d2 = d1 + 1; t2 = 0; }
        const float* w1 = cv + d1 * S_LEN + t1;
        const float* w2 = cv + d2 * S_LEN + t2;
        float y[32];
        #pragma unroll
        for (int k = 0; k < 16; k++) { y[k] = w1[k]; y[16 + k] = w2[k]; }
        float sy = 0.f;
        #pragma unroll
        for (int k = 0; k < 32; k++) sy += y[k];
        float mean = sy * (1.0f / 32.0f);
        float syy = 0.f, sxy = 0.f;
        #pragma unroll
        for (int k = 0; k < 32; k++) {
            float v = y[k] - mean;
            syy = fmaf(v, v, syy);
            sxy = fmaf(v, (float)k - 15.5f, sxy);
        }
        float r2 = (sxy * sxy) / (SXX_CONST * syy);   // syy==0 -> NaN -> false
        cm[i] = (r2 >= 0.5f) ? 1 : 0;
    }
    if (tid == 0) cm[NCAND - 1] = 0;
    __syncthreads();

    // ---- chunk-local function composition: element i is s -> (s & cm_i) ^ cm_i ----
    const int base = tid * CH;
    int fa = 1, fb = 0;                  // identity
    #pragma unroll
    for (int q = 0; q < CH; q++) {
        int i  = base + q;
        int ci = (i < NCAND) ? cm[i] : 0;
        fb = (fb & ci) ^ ci;
        fa &= ci;
    }
    int f = fa | (fb << 1);

    // ---- two-level non-commutative inclusive scan (shuffle) ----
    int finc = f;
    #pragma unroll
    for (int off = 1; off < 32; off <<= 1) {
        int g = __shfl_up_sync(0xffffffffu, finc, off);
        if (lane >= off) finc = fcomb(g, finc);
    }
    if (lane == 31) warpf[wid] = finc;
    __syncthreads();
    if (wid == 0) {
        int wf = (lane < NWARP) ? warpf[lane] : 1;
        #pragma unroll
        for (int off = 1; off < NWARP; off <<= 1) {
            int g = __shfl_up_sync(0xffffffffu, wf, off);
            if (lane >= off) wf = fcomb(g, wf);
        }
        if (lane < NWARP) warpf[lane] = wf;     // inclusive per-warp prefix
    }
    __syncthreads();
    int fex = __shfl_up_sync(0xffffffffu, finc, 1);
    if (lane == 0) fex = 1;                     // identity
    if (wid > 0)  fex = fcomb(warpf[wid - 1], fex);
    int s = (fex >> 1) & 1;                     // apply to initial state 0

    // ---- emit merge/valid bits + chunk count ----
    uint32_t mbits = 0, vbits = 0;
    int cnt = 0;
    #pragma unroll
    for (int q = 0; q < CH; q++) {
        int i = base + q;
        if (i >= NCAND) break;
        int v  = s ^ 1;
        int mg = v & cm[i];
        mbits |= (uint32_t)mg << q;
        vbits |= (uint32_t)v  << q;
        cnt += v;
        s = mg;
    }

    // ---- two-level add scan of counts ----
    int cinc = cnt;
    #pragma unroll
    for (int off = 1; off < 32; off <<= 1) {
        int g = __shfl_up_sync(0xffffffffu, cinc, off);
        if (lane >= off) cinc += g;
    }
    if (lane == 31) warpc[wid] = cinc;
    __syncthreads();
    if (wid == 0) {
        int wc = (lane < NWARP) ? warpc[lane] : 0;
        #pragma unroll
        for (int off = 1; off < NWARP; off <<= 1) {
            int g = __shfl_up_sync(0xffffffffu, wc, off);
            if (lane >= off) wc += g;
        }
        if (lane < NWARP) warpc[lane] = wc;
        if (lane == NWARP - 1) warpc[NWARP] = wc;   // total
    }
    __syncthreads();
    int pos = __shfl_up_sync(0xffffffffu, cinc, 1);
    if (lane == 0) pos = 0;
    if (wid > 0) pos += warpc[wid - 1];

    // ---- compaction: packed gather codes (t:12 | d:2 | merged:1) ----
    uint32_t* srow = g_src + (size_t)row * NCAND;
    for (int q = 0; q < CH; q++) {
        int i = base + q;
        if (i >= NCAND) break;
        if ((vbits >> q) & 1) {
            int d1 = i / NWIN;
            int t1 = i - d1 * NWIN;
            uint32_t code = (uint32_t)t1 | ((uint32_t)d1 << 12)
                          | (((mbits >> q) & 1u) << 14);
            srow[pos++] = code;
        }
    }
    int V = warpc[NWARP];
    for (int j = V + tid; j < NCAND; j += NT) srow[j] = 0xFFFFFFFFu;
}

// ---- output gather + transpose: out[b, n, k, c], c fastest.
// Block = 16 n-values x 16 k. Codes staged in shared; all 16 value loads
// issued independently (branch-free) for max MLP. ----
__global__ __launch_bounds__(256) void k_out(float* __restrict__ out)
{
    __shared__ uint32_t scode[8 * 16];        // [c][n_local]

    const int b   = blockIdx.y;
    const int n0  = blockIdx.x * 16;
    const int tid = threadIdx.x;

    if (tid < 128) {
        int cc = tid >> 4, nl = tid & 15;
        int n = n0 + nl;
        scode[tid] = (n < NCAND)
                   ? __ldg(&g_src[(size_t)(b * 8 + cc) * NCAND + n])
                   : 0xFFFFFFFFu;
    }
    __syncthreads();

    const int k  = tid & 15;
    const int nl = tid >> 4;
    const int n  = n0 + nl;
    if (n >= NCAND) return;

    const float* crb = g_conv + (size_t)(b * 8) * ND * S_LEN;

    uint32_t code[8];
    const float* p1[8];
    const float* p2[8];
    #pragma unroll
    for (int c = 0; c < 8; c++) {
        uint32_t cd = scode[c * 16 + nl];
        code[c] = cd;
        uint32_t safe = (cd == 0xFFFFFFFFu) ? 0u : cd;
        int t1 = safe & 0xFFF;
        int d1 = (safe >> 12) & 3;
        const float* cr = crb + (size_t)c * (ND * S_LEN);
        const float* a1 = cr + d1 * S_LEN + t1 + k;
        const float* a2 = a1;
        if (safe & (1u << 14)) {                  // merged with next candidate
            int t2 = t1 + 1, d2 = d1;
            if (t2 == NWIN) { t2 = 0; d2 = d1 + 1; }
            a2 = cr + d2 * S_LEN + t2 + k;
        }
        p1[c] = a1; p2[c] = a2;
    }

    float v1[8], v2[8];
    #pragma unroll
    for (int c = 0; c < 8; c++) v1[c] = __ldg(p1[c]);
    #pragma unroll
    for (int c = 0; c < 8; c++) v2[c] = __ldg(p2[c]);

    float buf[8];
    #pragma unroll
    for (int c = 0; c < 8; c++) {
        float v = (code[c] & (1u << 14)) ? 0.5f * (v1[c] + v2[c]) : v1[c];
        buf[c] = (code[c] == 0xFFFFFFFFu) ? 0.0f : v;
    }

    size_t obase = ((size_t)((b * NCAND + n) * PATCH + k)) * 8;
    float4* o = (float4*)(out + obase);
    o[0] = make_float4(buf[0], buf[1], buf[2], buf[3]);
    o[1] = make_float4(buf[4], buf[5], buf[6], buf[7]);
}

extern "C" void kernel_launch(void* const* d_in, const int* in_sizes, int n_in,
                              void* d_out, int out_size)
{
    const float* seasonal = (const float*)d_in[0];
    const float* cw       = (const float*)d_in[1];
    const float* cb       = (const float*)d_in[2];
    float* out = (float*)d_out;

    cudaFuncSetAttribute(k_row, cudaFuncAttributeMaxDynamicSharedMemorySize,
                         SMEM_BYTES);
    k_row<<<NROWS, NT, SMEM_BYTES>>>(seasonal, cw, cb);

    dim3 g((NCAND + 15) / 16, NB);
    k_out<<<g, 256>>>(out);
}

// round 5
// speedup vs baseline: 1.3895x; 1.3226x over previous
#include <cuda_runtime.h>
#include <stdint.h>

// Problem constants
#define S_LEN   2048
#define PATCH   16
#define NWIN    2033            // S_LEN - PATCH + 1
#define ND      4
#define NCAND   (ND * NWIN)     // 8132
#define NB      32
#define NC      8
#define NROWS   (NB * NC)       // 256
#define NT      512             // threads in row kernel
#define NWARP   (NT / 32)       // 16
#define CH      16              // chunk per thread (NT*CH = 8192 >= NCAND)
#define SXX_CONST 2728.0f       // sum_{k=0}^{31} (k-15.5)^2
#define CONV_ELEMS ((size_t)NROWS * ND * S_LEN)

// Scratch (static device globals; allocation-free).
// +16 zero pad: .bss is zero-initialized and k_row never writes it, so
// invalid gather codes can safely read 0.0f from the pad.
__device__ float    g_conv[CONV_ELEMS + 16];
__device__ uint32_t g_src[(size_t)NROWS * NCAND];

#define PAD_BYTE_OFF ((uint32_t)(CONV_ELEMS * 4))

// Shared layout for k_row (floats/bytes):
//  xs: 2048 f | cv: 8192 f | ws: 64 f | wb: 4 f | cm: 8136 B | warpf: 16 i | warpc: 17 i
#define SMEM_BYTES (8192 + 32768 + 256 + 16 + 8136 + 64 + 68 + 64)

// affine bit-function f(s) = (s & a) ^ b, packed as a | (b<<1).
// fcomb(first, second) = second ∘ first.
__device__ __forceinline__ int fcomb(int f1, int f2) {
    int a1 = f1 & 1, b1 = (f1 >> 1) & 1;
    int a2 = f2 & 1, b2 = (f2 >> 1) & 1;
    return (a1 & a2) | ((((b1 & a2) ^ b2)) << 1);
}

__global__ __launch_bounds__(NT) void k_row(
    const float* __restrict__ seasonal,
    const float* __restrict__ conv_w,
    const float* __restrict__ conv_b)
{
    extern __shared__ unsigned char smem_raw[];
    float*   xs    = (float*)smem_raw;
    float*   cv    = xs + S_LEN;
    float*   ws    = cv + ND * S_LEN;
    float*   wb    = ws + 64;
    uint8_t* cm    = (uint8_t*)(wb + 4);
    int*     warpf = (int*)(cm + 8136);
    int*     warpc = warpf + NWARP;     // [NWARP+1]

    const int row  = blockIdx.x;         // b*8 + c
    const int b    = row >> 3;
    const int c    = row & 7;
    const int tid  = threadIdx.x;
    const int lane = tid & 31;
    const int wid  = tid >> 5;

    // ---- stage weights + input row ----
    if (tid < 64) ws[tid] = conv_w[tid];
    if (tid < 4)  wb[tid] = conv_b[tid];
    for (int s = tid; s < S_LEN; s += NT)
        xs[s] = seasonal[((size_t)b * S_LEN + s) * NC + c];
    __syncthreads();

    // ---- dilated conv ----
    float* grow = g_conv + (size_t)row * ND * S_LEN;
    for (int idx = tid; idx < ND * S_LEN; idx += NT) {
        int di  = idx >> 11;
        int t   = idx & (S_LEN - 1);
        int dil = 1 << di;
        float acc = wb[di];
        #pragma unroll
        for (int k = 0; k < PATCH; k++) {
            int j = t - (15 - k) * dil;
            float xv = (j >= 0) ? xs[j] : 0.0f;
            acc = fmaf(ws[di * PATCH + k], xv, acc);
        }
        cv[idx]   = acc;
        grow[idx] = acc;
    }
    __syncthreads();

    // ---- can_merge via rolling window raw moments ----
    // window(t) of row d: S1=Σ_{j<16} y[t+j], S2=Σ y², M=Σ y·j
    // pair(i): sy=S1(t)+S1(t+1); sy2=S2(t)+S2(t+1); syk=M(t)+M(t+1)+16·S1(t+1)
    // sxy = syk − 15.5·sy ; syy = sy2 − sy²/32 ; r2 = sxy²/(2728·syy)
    {
        const int base = tid * CH;
        int   cur_d = -1, cur_t = -1;
        float S1 = 0.f, S2 = 0.f, M = 0.f;
        const float* rowp = cv;
        for (int q = 0; q < CH; q++) {
            int i = base + q;
            if (i >= NCAND - 1) break;
            int d1 = i / NWIN;
            int t1 = i - d1 * NWIN;
            if (t1 == NWIN - 1) {
                // cross-dilation pair: direct 32-element evaluation
                const float* w1 = cv + d1 * S_LEN + t1;
                const float* w2 = cv + (d1 + 1) * S_LEN;
                float s = 0.f, s2 = 0.f, sk = 0.f;
                #pragma unroll
                for (int k = 0; k < 16; k++) {
                    float y = w1[k];
                    s += y; s2 = fmaf(y, y, s2); sk = fmaf(y, (float)k, sk);
                }
                #pragma unroll
                for (int k = 0; k < 16; k++) {
                    float y = w2[k];
                    s += y; s2 = fmaf(y, y, s2); sk = fmaf(y, (float)(16 + k), sk);
                }
                float sxy = sk - 15.5f * s;
                float syy = s2 - s * s * (1.0f / 32.0f);
                float r2 = (sxy * sxy) / (SXX_CONST * syy);
                cm[i] = (r2 >= 0.5f) ? 1 : 0;
                cur_d = -1;
                continue;
            }
            if (d1 != cur_d || t1 != cur_t) {
                rowp = cv + d1 * S_LEN;
                S1 = 0.f; S2 = 0.f; M = 0.f;
                #pragma unroll
                for (int k = 0; k < 16; k++) {
                    float y = rowp[t1 + k];
                    S1 += y; S2 = fmaf(y, y, S2); M = fmaf(y, (float)k, M);
                }
                cur_d = d1;
            }
            float y0  = rowp[t1];
            float y16 = rowp[t1 + 16];
            float S1n = S1 - y0 + y16;
            float S2n = S2 - y0 * y0 + y16 * y16;
            float Mn  = M + 15.0f * y16 + y0 - S1;
            float sy  = S1 + S1n;
            float sy2 = S2 + S2n;
            float syk = M + Mn + 16.0f * S1n;
            float sxy = syk - 15.5f * sy;
            float syy = sy2 - sy * sy * (1.0f / 32.0f);
            float r2 = (sxy * sxy) / (SXX_CONST * syy);  // syy<=0 -> NaN/neg -> false
            cm[i] = (r2 >= 0.5f) ? 1 : 0;
            S1 = S1n; S2 = S2n; M = Mn;
            cur_t = t1 + 1;
        }
    }
    if (tid == 0) cm[NCAND - 1] = 0;
    __syncthreads();

    // ---- chunk-local function composition (s -> (s & cm_i) ^ cm_i) ----
    const int base = tid * CH;
    int fa = 1, fb = 0;
    #pragma unroll
    for (int q = 0; q < CH; q++) {
        int i  = base + q;
        int ci = (i < NCAND) ? cm[i] : 0;
        fb = (fb & ci) ^ ci;
        fa &= ci;
    }
    int f = fa | (fb << 1);

    // ---- two-level non-commutative scan ----
    int finc = f;
    #pragma unroll
    for (int off = 1; off < 32; off <<= 1) {
        int g = __shfl_up_sync(0xffffffffu, finc, off);
        if (lane >= off) finc = fcomb(g, finc);
    }
    if (lane == 31) warpf[wid] = finc;
    __syncthreads();
    if (wid == 0) {
        int wf = (lane < NWARP) ? warpf[lane] : 1;
        #pragma unroll
        for (int off = 1; off < NWARP; off <<= 1) {
            int g = __shfl_up_sync(0xffffffffu, wf, off);
            if (lane >= off) wf = fcomb(g, wf);
        }
        if (lane < NWARP) warpf[lane] = wf;
    }
    __syncthreads();
    int fex = __shfl_up_sync(0xffffffffu, finc, 1);
    if (lane == 0) fex = 1;
    if (wid > 0)  fex = fcomb(warpf[wid - 1], fex);
    int s = (fex >> 1) & 1;

    // ---- emit merge/valid bits + counts ----
    uint32_t mbits = 0, vbits = 0;
    int cnt = 0;
    #pragma unroll
    for (int q = 0; q < CH; q++) {
        int i = base + q;
        if (i >= NCAND) break;
        int v  = s ^ 1;
        int mg = v & cm[i];
        mbits |= (uint32_t)mg << q;
        vbits |= (uint32_t)v  << q;
        cnt += v;
        s = mg;
    }

    // ---- two-level add scan ----
    int cinc = cnt;
    #pragma unroll
    for (int off = 1; off < 32; off <<= 1) {
        int g = __shfl_up_sync(0xffffffffu, cinc, off);
        if (lane >= off) cinc += g;
    }
    if (lane == 31) warpc[wid] = cinc;
    __syncthreads();
    if (wid == 0) {
        int wc = (lane < NWARP) ? warpc[lane] : 0;
        #pragma unroll
        for (int off = 1; off < NWARP; off <<= 1) {
            int g = __shfl_up_sync(0xffffffffu, wc, off);
            if (lane >= off) wc += g;
        }
        if (lane < NWARP) warpc[lane] = wc;
        if (lane == NWARP - 1) warpc[NWARP] = wc;
    }
    __syncthreads();
    int pos = __shfl_up_sync(0xffffffffu, cinc, 1);
    if (lane == 0) pos = 0;
    if (wid > 0) pos += warpc[wid - 1];

    // ---- compaction: packed gather codes (t:12 | d:2 | merged:1) ----
    uint32_t* srow = g_src + (size_t)row * NCAND;
    for (int q = 0; q < CH; q++) {
        int i = base + q;
        if (i >= NCAND) break;
        if ((vbits >> q) & 1) {
            int d1 = i / NWIN;
            int t1 = i - d1 * NWIN;
            uint32_t code = (uint32_t)t1 | ((uint32_t)d1 << 12)
                          | (((mbits >> q) & 1u) << 14);
            srow[pos++] = code;
        }
    }
    int V = warpc[NWARP];
    for (int j = V + tid; j < NCAND; j += NT) srow[j] = 0xFFFFFFFFu;
}

// ---- output gather + transpose: out[b, n, k, c], c fastest.
// 128 threads precompute 32-bit absolute byte offsets (merge flag in bit 31
// of off2) once per (c, n); main loop is LDS-broadcast + IADD + LDG with the
// second load predicated on the (rare) merge flag. Stores streamed (__stcs)
// so the 133 MB output doesn't evict the 8 MB conv table from L2. ----
__global__ __launch_bounds__(256) void k_out(float* __restrict__ out)
{
    __shared__ uint32_t soff1[8][16];
    __shared__ uint32_t soff2[8][16];

    const int b   = blockIdx.y;
    const int n0  = blockIdx.x * 16;
    const int tid = threadIdx.x;

    if (tid < 128) {
        int cc = tid >> 4, nl = tid & 15;
        int n = n0 + nl;
        uint32_t cd = (n < NCAND)
                    ? __ldcs(&g_src[(size_t)(b * 8 + cc) * NCAND + n])
                    : 0xFFFFFFFFu;
        uint32_t o1, o2;
        if (cd == 0xFFFFFFFFu) {
            o1 = PAD_BYTE_OFF; o2 = PAD_BYTE_OFF;
        } else {
            int t1 = cd & 0xFFF;
            int d1 = (cd >> 12) & 3;
            uint32_t rbase = (uint32_t)((b * 8 + cc) * ND * S_LEN) * 4u;
            o1 = rbase + (uint32_t)(d1 * S_LEN + t1) * 4u;
            if (cd & (1u << 14)) {
                int t2 = t1 + 1, d2 = d1;
                if (t2 == NWIN) { t2 = 0; d2 = d1 + 1; }
                o2 = (rbase + (uint32_t)(d2 * S_LEN + t2) * 4u) | 0x80000000u;
            } else {
                o2 = o1;
            }
        }
        soff1[cc][nl] = o1;
        soff2[cc][nl] = o2;
    }
    __syncthreads();

    const int k  = tid & 15;
    const int nl = tid >> 4;
    const int n  = n0 + nl;
    if (n >= NCAND) return;

    const char* gp = (const char*)g_conv;
    const uint32_t k4 = (uint32_t)(k << 2);

    float buf[8];
    #pragma unroll
    for (int c = 0; c < 8; c++) {
        uint32_t o1  = soff1[c][nl] + k4;
        uint32_t o2w = soff2[c][nl];
        float v1 = __ldg((const float*)(gp + o1));
        float v  = v1;
        if (o2w & 0x80000000u) {
            float v2 = __ldg((const float*)(gp + (o2w & 0x7FFFFFFFu) + k4));
            v = 0.5f * (v1 + v2);
        }
        buf[c] = v;
    }

    size_t obase = ((size_t)((b * NCAND + n) * PATCH + k)) * 8;
    float4* o = (float4*)(out + obase);
    __stcs(o,     make_float4(buf[0], buf[1], buf[2], buf[3]));
    __stcs(o + 1, make_float4(buf[4], buf[5], buf[6], buf[7]));
}

extern "C" void kernel_launch(void* const* d_in, const int* in_sizes, int n_in,
                              void* d_out, int out_size)
{
    const float* seasonal = (const float*)d_in[0];
    const float* cw       = (const float*)d_in[1];
    const float* cb       = (const float*)d_in[2];
    float* out = (float*)d_out;

    cudaFuncSetAttribute(k_row, cudaFuncAttributeMaxDynamicSharedMemorySize,
                         SMEM_BYTES);
    k_row<<<NROWS, NT, SMEM_BYTES>>>(seasonal, cw, cb);

    dim3 g((NCAND + 15) / 16, NB);
    k_out<<<g, 256>>>(out);
}

// round 8
// speedup vs baseline: 1.5102x; 1.0869x over previous
#include <cuda_runtime.h>
#include <stdint.h>

// Problem constants
#define S_LEN   2048
#define PATCH   16
#define NWIN    2033            // S_LEN - PATCH + 1
#define ND      4
#define NCAND   (ND * NWIN)     // 8132
#define NB      32
#define NC      8
#define NROWS   (NB * NC)       // 256
#define NT      512
#define NWARP   (NT / 32)       // 16
#define CH      16              // chunk per thread (NT*CH = 8192 >= NCAND)
#define SXX_CONST 2728.0f       // sum_{k=0}^{31} (k-15.5)^2
#define CONV_ELEMS ((size_t)NROWS * ND * S_LEN)

// Scratch (static device globals; allocation-free).
// +16 zero pad: .bss zero-init, never written -> invalid gathers read 0.0f.
__device__ float    g_conv[CONV_ELEMS + 16];
__device__ uint32_t g_src[(size_t)NROWS * NCAND];

#define PAD_BYTE_OFF ((uint32_t)(CONV_ELEMS * 4))

// affine bit-function f(s) = (s & a) ^ b, packed as a | (b<<1).
// fcomb(first, second) = second ∘ first.
__device__ __forceinline__ int fcomb(int f1, int f2) {
    int a1 = f1 & 1, b1 = (f1 >> 1) & 1;
    int a2 = f2 & 1, b2 = (f2 >> 1) & 1;
    return (a1 & a2) | ((((b1 & a2) ^ b2)) << 1);
}

// ============================ K_conv =====================================
// One block per row. Stage xs in shared, write 4 dilated conv rows to global.
__global__ __launch_bounds__(NT) void k_conv(
    const float* __restrict__ seasonal,
    const float* __restrict__ conv_w,
    const float* __restrict__ conv_b)
{
    __shared__ float xs[S_LEN];
    __shared__ float ws[64];
    __shared__ float wb[4];

    const int row = blockIdx.x;          // b*8 + c
    const int b   = row >> 3;
    const int c   = row & 7;
    const int tid = threadIdx.x;

    if (tid < 64) ws[tid] = conv_w[tid];
    if (tid < 4)  wb[tid] = conv_b[tid];
    for (int s = tid; s < S_LEN; s += NT)
        xs[s] = seasonal[((size_t)b * S_LEN + s) * NC + c];
    __syncthreads();

    float* grow = g_conv + (size_t)row * ND * S_LEN;
    #pragma unroll
    for (int u = 0; u < (ND * S_LEN) / NT; u++) {
        int idx = u * NT + tid;
        int di  = idx >> 11;
        int t   = idx & (S_LEN - 1);
        int dil = 1 << di;
        float acc = wb[di];
        #pragma unroll
        for (int k = 0; k < PATCH; k++) {
            int j = t - (15 - k) * dil;
            float xv = (j >= 0) ? xs[j] : 0.0f;
            acc = fmaf(ws[di * PATCH + k], xv, acc);
        }
        grow[idx] = acc;
    }
}

// ============================ K_scan =====================================
// One slim block per row: rolling-moment R^2 (register bitmask), warp-shuffle
// scans, compaction into packed gather codes (t:12 | d:2 | merged:1).
__global__ __launch_bounds__(NT) void k_scan()
{
    __shared__ int warpf[NWARP];
    __shared__ int warpc[NWARP + 1];

    const int row  = blockIdx.x;
    const int tid  = threadIdx.x;
    const int lane = tid & 31;
    const int wid  = tid >> 5;

    const float* crow = g_conv + (size_t)row * ND * S_LEN;
    const int base = tid * CH;

    // ---- can_merge bits for this thread's 16 pairs ----
    uint32_t cmask = 0;
    {
        int d1 = base / NWIN;
        int t1 = base - d1 * NWIN;
        bool need_init = true;
        float S1 = 0.f, S2 = 0.f, M = 0.f;
        const float* rowp = crow + d1 * S_LEN;
        #pragma unroll 1
        for (int q = 0; q < CH; q++) {
            int i = base + q;
            if (i >= NCAND - 1) break;
            if (t1 == NWIN - 1) {
                // cross-dilation pair: direct 32-element evaluation
                const float* w1 = crow + d1 * S_LEN + t1;
                const float* w2 = crow + (d1 + 1) * S_LEN;
                float s = 0.f, s2 = 0.f, sk = 0.f;
                #pragma unroll
                for (int k = 0; k < 16; k++) {
                    float y = w1[k];
                    s += y; s2 = fmaf(y, y, s2); sk = fmaf(y, (float)k, sk);
                }
                #pragma unroll
                for (int k = 0; k < 16; k++) {
                    float y = w2[k];
                    s += y; s2 = fmaf(y, y, s2); sk = fmaf(y, (float)(16 + k), sk);
                }
                float sxy = sk - 15.5f * s;
                float syy = s2 - s * s * (1.0f / 32.0f);
                float r2 = (sxy * sxy) / (SXX_CONST * syy);
                if (r2 >= 0.5f) cmask |= 1u << q;
                d1++; t1 = 0;
                rowp = crow + d1 * S_LEN;
                need_init = true;
                continue;
            }
            if (need_init) {
                S1 = 0.f; S2 = 0.f; M = 0.f;
                #pragma unroll
                for (int k = 0; k < 16; k++) {
                    float y = rowp[t1 + k];
                    S1 += y; S2 = fmaf(y, y, S2); M = fmaf(y, (float)k, M);
                }
                need_init = false;
            }
            float y0  = rowp[t1];
            float y16 = rowp[t1 + 16];
            float S1n = S1 - y0 + y16;
            float S2n = S2 - y0 * y0 + y16 * y16;
            float Mn  = M + 15.0f * y16 + y0 - S1;
            float sy  = S1 + S1n;
            float sy2 = S2 + S2n;
            float syk = M + Mn + 16.0f * S1n;
            float sxy = syk - 15.5f * sy;
            float syy = sy2 - sy * sy * (1.0f / 32.0f);
            float r2 = (sxy * sxy) / (SXX_CONST * syy);  // syy<=0 -> NaN -> false
            if (r2 >= 0.5f) cmask |= 1u << q;
            S1 = S1n; S2 = S2n; M = Mn;
            t1++;
        }
    }

    // ---- chunk function in closed form from cmask ----
    // all-16-ones -> identity; else a=0, b = parity of trailing-ones run.
    int f;
    {
        uint32_t t = (~cmask) & 0xFFFFu;
        if (t == 0) f = 1;                          // a=1, b=0
        else {
            int hz = 31 - __clz(t);                 // highest zero position
            int L  = 15 - hz;                       // trailing ones
            f = (L & 1) << 1;                       // a=0
        }
    }

    // ---- two-level non-commutative scan ----
    int finc = f;
    #pragma unroll
    for (int off = 1; off < 32; off <<= 1) {
        int g = __shfl_up_sync(0xffffffffu, finc, off);
        if (lane >= off) finc = fcomb(g, finc);
    }
    if (lane == 31) warpf[wid] = finc;
    __syncthreads();
    if (wid == 0) {
        int wf = (lane < NWARP) ? warpf[lane] : 1;
        #pragma unroll
        for (int off = 1; off < NWARP; off <<= 1) {
            int g = __shfl_up_sync(0xffffffffu, wf, off);
            if (lane >= off) wf = fcomb(g, wf);
        }
        if (lane < NWARP) warpf[lane] = wf;
    }
    __syncthreads();
    int fex = __shfl_up_sync(0xffffffffu, finc, 1);
    if (lane == 0) fex = 1;
    if (wid > 0)  fex = fcomb(warpf[wid - 1], fex);
    int s = (fex >> 1) & 1;

    // ---- emit merge/valid bits + counts ----
    uint32_t mbits = 0, vbits = 0;
    int cnt = 0;
    #pragma unroll
    for (int q = 0; q < CH; q++) {
        int i = base + q;
        if (i >= NCAND) break;
        int ci = (cmask >> q) & 1;
        int v  = s ^ 1;
        int mg = v & ci;
        mbits |= (uint32_t)mg << q;
        vbits |= (uint32_t)v  << q;
        cnt += v;
        s = mg;
    }

    // ---- two-level add scan ----
    int cinc = cnt;
    #pragma unroll
    for (int off = 1; off < 32; off <<= 1) {
        int g = __shfl_up_sync(0xffffffffu, cinc, off);
        if (lane >= off) cinc += g;
    }
    if (lane == 31) warpc[wid] = cinc;
    __syncthreads();
    if (wid == 0) {
        int wc = (lane < NWARP) ? warpc[lane] : 0;
        #pragma unroll
        for (int off = 1; off < NWARP; off <<= 1) {
            int g = __shfl_up_sync(0xffffffffu, wc, off);
            if (lane >= off) wc += g;
        }
        if (lane < NWARP) warpc[lane] = wc;
        if (lane == NWARP - 1) warpc[NWARP] = wc;
    }
    __syncthreads();
    int pos = __shfl_up_sync(0xffffffffu, cinc, 1);
    if (lane == 0) pos = 0;
    if (wid > 0) pos += warpc[wid - 1];

    // ---- compaction ----
    uint32_t* srow = g_src + (size_t)row * NCAND;
    {
        int d1 = base / NWIN;
        int t1 = base - d1 * NWIN;
        #pragma unroll 1
        for (int q = 0; q < CH; q++) {
            int i = base + q;
            if (i >= NCAND) break;
            if ((vbits >> q) & 1) {
                uint32_t code = (uint32_t)t1 | ((uint32_t)d1 << 12)
                              | (((mbits >> q) & 1u) << 14);
                srow[pos++] = code;
            }
            if (++t1 == NWIN) { t1 = 0; d1++; }
        }
    }
    int V = warpc[NWARP];
    for (int j = V + tid; j < NCAND; j += NT) srow[j] = 0xFFFFFFFFu;
}

// ============================ k_out ======================================
// out[b, n, k, c], c fastest. Block = 32 n x 16 k, each thread handles TWO
// independent n (ILP). Per-(c,n) absolute byte offsets precomputed in shared
// (merge flag in bit 31 of o2). Streamed stores keep conv table in L2.
__global__ __launch_bounds__(256) void k_out(float* __restrict__ out)
{
    __shared__ uint2 soff[8][32];     // [c][n_local] = (o1, o2|mergeflag)

    const int b   = blockIdx.y;
    const int n0  = blockIdx.x * 32;
    const int tid = threadIdx.x;

    {
        int cc = tid >> 5, nj = tid & 31;
        int n = n0 + nj;
        uint32_t cd = (n < NCAND)
                    ? __ldcs(&g_src[(size_t)(b * 8 + cc) * NCAND + n])
                    : 0xFFFFFFFFu;
        uint32_t o1, o2;
        if (cd == 0xFFFFFFFFu) {
            o1 = PAD_BYTE_OFF; o2 = PAD_BYTE_OFF;
        } else {
            int t1 = cd & 0xFFF;
            int d1 = (cd >> 12) & 3;
            uint32_t rbase = (uint32_t)((b * 8 + cc) * ND * S_LEN) * 4u;
            o1 = rbase + (uint32_t)(d1 * S_LEN + t1) * 4u;
            if (cd & (1u << 14)) {
                int t2 = t1 + 1, d2 = d1;
                if (t2 == NWIN) { t2 = 0; d2 = d1 + 1; }
                o2 = (rbase + (uint32_t)(d2 * S_LEN + t2) * 4u) | 0x80000000u;
            } else {
                o2 = o1;
            }
        }
        soff[cc][nj] = make_uint2(o1, o2);
    }
    __syncthreads();

    const int k  = tid & 15;
    const int nl = tid >> 4;          // 0..15
    const char* gp = (const char*)g_conv;
    const uint32_t k4 = (uint32_t)(k << 2);

    const int nA = n0 + nl;
    const int nB = n0 + nl + 16;

    float bufA[8], bufB[8];
    #pragma unroll
    for (int c = 0; c < 8; c++) {
        uint2 oa = soff[c][nl];
        uint2 ob = soff[c][nl + 16];
        float va1 = __ldg((const float*)(gp + oa.x + k4));
        float vb1 = __ldg((const float*)(gp + ob.x + k4));
        float va = va1, vb = vb1;
        if (oa.y & 0x80000000u) {
            float va2 = __ldg((const float*)(gp + (oa.y & 0x7FFFFFFFu) + k4));
            va = 0.5f * (va1 + va2);
        }
        if (ob.y & 0x80000000u) {
            float vb2 = __ldg((const float*)(gp + (ob.y & 0x7FFFFFFFu) + k4));
            vb = 0.5f * (vb1 + vb2);
        }
        bufA[c] = va;
        bufB[c] = vb;
    }

    if (nA < NCAND) {
        size_t obase = ((size_t)((b * NCAND + nA) * PATCH + k)) * 8;
        float4* o = (float4*)(out + obase);
        __stcs(o,     make_float4(bufA[0], bufA[1], bufA[2], bufA[3]));
        __stcs(o + 1, make_float4(bufA[4], bufA[5], bufA[6], bufA[7]));
    }
    if (nB < NCAND) {
        size_t obase = ((size_t)((b * NCAND + nB) * PATCH + k)) * 8;
        float4* o = (float4*)(out + obase);
        __stcs(o,     make_float4(bufB[0], bufB[1], bufB[2], bufB[3]));
        __stcs(o + 1, make_float4(bufB[4], bufB[5], bufB[6], bufB[7]));
    }
}

extern "C" void kernel_launch(void* const* d_in, const int* in_sizes, int n_in,
                              void* d_out, int out_size)
{
    const float* seasonal = (const float*)d_in[0];
    const float* cw       = (const float*)d_in[1];
    const float* cb       = (const float*)d_in[2];
    float* out = (float*)d_out;

    k_conv<<<NROWS, NT>>>(seasonal, cw, cb);
    k_scan<<<NROWS, NT>>>();

    dim3 g((NCAND + 31) / 32, NB);
    k_out<<<g, 256>>>(out);
}